// round 5
// baseline (speedup 1.0000x reference)
#include <cuda_runtime.h>

using u64 = unsigned long long;

// ---------------- problem constants (fixed shapes) -------------------------
constexpr int Bn = 4;
constexpr int Nn = 8192;
constexpr int Cc = 32;
constexpr int M2 = 8192;
constexpr int M3 = 4096;
constexpr int M4 = 2048;
constexpr int MM = 4096;

constexpr int Q     = 4;           // queries per lane
constexpr int QPB   = 128;         // queries per block (32 lanes * Q)
constexpr int PARTS = 8;           // warps per block (candidate partitions)
constexpr int NT    = 256;
constexpr float BIG = 3.0e38f;

// ---------------- device scratch (SoA, 16B-aligned for LDG.128) ------------
__device__ __align__(16) float g2x[Bn*M2], g2y[Bn*M2], g2z[Bn*M2], g2w[Bn*M2], g2f[Bn*M2];
__device__ __align__(16) float g3x[Bn*M3], g3y[Bn*M3], g3z[Bn*M3], g3w[Bn*M3], g3f[Bn*M3];
__device__ __align__(16) float g4x[Bn*M4], g4y[Bn*M4], g4z[Bn*M4], g4w[Bn*M4], g4f[Bn*M4];
__device__ __align__(16) float gmx[Bn*MM], gmy[Bn*MM], gmz[Bn*MM], gmw[Bn*MM];

// ---------------- packed f32x2 helpers (u64-native, no pack MOVs) ----------
__device__ __forceinline__ u64 ffma2u(u64 a, u64 b, u64 c) {
    u64 r;
    asm("fma.rn.f32x2 %0, %1, %2, %3;" : "=l"(r) : "l"(a), "l"(b), "l"(c));
    return r;
}
__device__ __forceinline__ u64 fadd2u(u64 a, u64 b) {
    u64 r;
    asm("add.rn.f32x2 %0, %1, %2;" : "=l"(r) : "l"(a), "l"(b));
    return r;
}
__device__ __forceinline__ float lo_(u64 v) { return __uint_as_float((unsigned)v); }
__device__ __forceinline__ float hi_(u64 v) { return __uint_as_float((unsigned)(v >> 32)); }
__device__ __forceinline__ u64 dup2(float x) {
    unsigned b = __float_as_uint(x);
    return ((u64)b << 32) | (u64)b;
}

// ---------------- single fused precompute kernel ----------------------------
__device__ __forceinline__ void pack_one(
    const float* __restrict__ known, const float* __restrict__ feats, int i,
    float* px, float* py, float* pz, float* pw, float* pf,
    const float* sv, int voff)
{
    float x = known[3 * i + 0];
    float y = known[3 * i + 1];
    float z = known[3 * i + 2];
    // same rounding order as jnp.sum(known*known, -1)
    float kk = __fadd_rn(__fadd_rn(__fmul_rn(x, x), __fmul_rn(y, y)), __fmul_rn(z, z));
    px[i] = x; py[i] = y; pz[i] = z; pw[i] = kk;

    float acc = 0.f;
    const float4* f4 = reinterpret_cast<const float4*>(feats + (size_t)i * Cc);
#pragma unroll
    for (int j = 0; j < 8; j++) {
        float4 t = f4[j];
        acc = fmaf(t.x, sv[voff + 4 * j + 0], acc);
        acc = fmaf(t.y, sv[voff + 4 * j + 1], acc);
        acc = fmaf(t.z, sv[voff + 4 * j + 2], acc);
        acc = fmaf(t.w, sv[voff + 4 * j + 3], acc);
    }
    pf[i] = acc;
}

__global__ void precompute_kernel(
    const float* __restrict__ known2, const float* __restrict__ feats2,
    const float* __restrict__ known3, const float* __restrict__ feats3,
    const float* __restrict__ known4, const float* __restrict__ feats4,
    const float* __restrict__ matchp,
    const float* __restrict__ w_fc, const float* __restrict__ w_cls)
{
    __shared__ float sv[96];                    // v = w_cls @ w_fc (per-block)
    int t = threadIdx.x;
    if (t < 96) {
        float acc = 0.f;
#pragma unroll
        for (int k = 0; k < 64; k++) acc = fmaf(w_cls[k], w_fc[k * 96 + t], acc);
        sv[t] = acc;
    }
    __syncthreads();

    int idx = blockIdx.x * NT + t;
    constexpr int A = Bn * M2;
    constexpr int B = A + Bn * M3;
    constexpr int C = B + Bn * M4;
    constexpr int D = C + Bn * MM;
    if (idx < A) {
        pack_one(known2, feats2, idx, g2x, g2y, g2z, g2w, g2f, sv, 0);
    } else if (idx < B) {
        pack_one(known3, feats3, idx - A, g3x, g3y, g3z, g3w, g3f, sv, 32);
    } else if (idx < C) {
        pack_one(known4, feats4, idx - B, g4x, g4y, g4z, g4w, g4f, sv, 64);
    } else if (idx < D) {
        int i = idx - C;
        float x = matchp[3 * i + 0];
        float y = matchp[3 * i + 1];
        float z = matchp[3 * i + 2];
        float kk = __fadd_rn(__fadd_rn(__fmul_rn(x, x), __fmul_rn(y, y)), __fmul_rn(z, z));
        gmx[i] = x; gmy[i] = y; gmz[i] = z; gmw[i] = kk;
    }
}

// ---------------- top-3 maintenance ------------------------------------------
__device__ __forceinline__ void try_ins(float e, float fv, float t[3], float f[3]) {
    if (e < t[2]) {
        if (e < t[1]) {
            t[2] = t[1]; f[2] = f[1];
            if (e < t[0]) { t[1] = t[0]; f[1] = f[0]; t[0] = e; f[0] = fv; }
            else          { t[1] = e;    f[1] = fv; }
        } else { t[2] = e; f[2] = fv; }
    }
}

// ---------------- interp scan: top-3 of d = (qq+kk) - 2*dot, from GLOBAL ----
// rounding order matches round-2/reference: s = qq+kk, then fma x, y, z
__device__ __forceinline__ void scan_set(
    const float* __restrict__ gx, const float* __restrict__ gy,
    const float* __restrict__ gz, const float* __restrict__ gw,
    const float* __restrict__ gf,
    int Mg, int part,
    const u64 c2x[Q], const u64 c2y[Q], const u64 c2z[Q], const u64 qq2[Q],
    float t[Q][3], float f[Q][3])
{
#pragma unroll
    for (int j = 0; j < Q; j++) {
        t[j][0] = t[j][1] = t[j][2] = BIG;
        f[j][0] = f[j][1] = f[j][2] = 0.f;
    }
    const ulonglong2* px = reinterpret_cast<const ulonglong2*>(gx) + part * Mg;
    const ulonglong2* py = reinterpret_cast<const ulonglong2*>(gy) + part * Mg;
    const ulonglong2* pz = reinterpret_cast<const ulonglong2*>(gz) + part * Mg;
    const ulonglong2* pw = reinterpret_cast<const ulonglong2*>(gw) + part * Mg;
    const float4*     pf = reinterpret_cast<const float4*>(gf)     + part * Mg;

#pragma unroll 2
    for (int g = 0; g < Mg; g++) {
        ulonglong2 X = __ldg(px + g);
        ulonglong2 Y = __ldg(py + g);
        ulonglong2 Z = __ldg(pz + g);
        ulonglong2 W = __ldg(pw + g);
        float4     F = __ldg(pf + g);
#pragma unroll
        for (int j = 0; j < Q; j++) {
            u64 dl = ffma2u(c2x[j], X.x, fadd2u(qq2[j], W.x));
            dl = ffma2u(c2y[j], Y.x, dl);
            dl = ffma2u(c2z[j], Z.x, dl);
            u64 dh = ffma2u(c2x[j], X.y, fadd2u(qq2[j], W.y));
            dh = ffma2u(c2y[j], Y.y, dh);
            dh = ffma2u(c2z[j], Z.y, dh);
            float d0 = lo_(dl), d1 = hi_(dl), d2 = lo_(dh), d3 = hi_(dh);
            float m = fminf(fminf(d0, d1), fminf(d2, d3));
            if (m < t[j][2]) {                    // register-only insert body
                try_ins(d0, F.x, t[j], f[j]);
                try_ins(d1, F.y, t[j], f[j]);
                try_ins(d2, F.z, t[j], f[j]);
                try_ins(d3, F.w, t[j], f[j]);
            }
        }
    }
}

// ---------------- mask scan: any(d2 < 0.25), margin + exact recheck ---------
__device__ __forceinline__ void scan_mask(
    const float* __restrict__ gx, const float* __restrict__ gy,
    const float* __restrict__ gz, const float* __restrict__ gw,
    int Mg, int part,
    const u64 c2x[Q], const u64 c2y[Q], const u64 c2z[Q], const u64 qq2[Q],
    bool found[Q])
{
    float tf[Q], qx[Q], qy[Q], qz[Q], qqv[Q];
#pragma unroll
    for (int j = 0; j < Q; j++) {
        found[j] = false;
        qqv[j] = lo_(qq2[j]);
        tf[j]  = 0.3125f - qqv[j];               // e < 0.25 + 0.0625 margin
        qx[j]  = -0.5f * lo_(c2x[j]);            // exact (pow2 scale)
        qy[j]  = -0.5f * lo_(c2y[j]);
        qz[j]  = -0.5f * lo_(c2z[j]);
    }
    const ulonglong2* px = reinterpret_cast<const ulonglong2*>(gx) + part * Mg;
    const ulonglong2* py = reinterpret_cast<const ulonglong2*>(gy) + part * Mg;
    const ulonglong2* pz = reinterpret_cast<const ulonglong2*>(gz) + part * Mg;
    const ulonglong2* pw = reinterpret_cast<const ulonglong2*>(gw) + part * Mg;

#pragma unroll 2
    for (int g = 0; g < Mg; g++) {
        ulonglong2 X = __ldg(px + g);
        ulonglong2 Y = __ldg(py + g);
        ulonglong2 Z = __ldg(pz + g);
        ulonglong2 W = __ldg(pw + g);
#pragma unroll
        for (int j = 0; j < Q; j++) {
            // fast path: e = kk - 2*dot (qq deferred; protected by margin)
            u64 el = ffma2u(c2x[j], X.x, ffma2u(c2y[j], Y.x, ffma2u(c2z[j], Z.x, W.x)));
            u64 eh = ffma2u(c2x[j], X.y, ffma2u(c2y[j], Y.y, ffma2u(c2z[j], Z.y, W.y)));
            float m = fminf(fminf(lo_(el), hi_(el)), fminf(lo_(eh), hi_(eh)));
            if (m < tf[j]) {                      // rare: exact recheck
                float cx[4] = { lo_(X.x), hi_(X.x), lo_(X.y), hi_(X.y) };
                float cy[4] = { lo_(Y.x), hi_(Y.x), lo_(Y.y), hi_(Y.y) };
                float cz[4] = { lo_(Z.x), hi_(Z.x), lo_(Z.y), hi_(Z.y) };
                float cw[4] = { lo_(W.x), hi_(W.x), lo_(W.y), hi_(W.y) };
#pragma unroll
                for (int c = 0; c < 4; c++) {
                    // bit-exact reference-mimic rounding
                    float dot = __fadd_rn(__fadd_rn(__fmul_rn(qx[j], cx[c]),
                                                    __fmul_rn(qy[j], cy[c])),
                                          __fmul_rn(qz[j], cz[c]));
                    float d = __fsub_rn(__fadd_rn(qqv[j], cw[c]),
                                        __fadd_rn(dot, dot));
                    if (d < 0.25f) found[j] = true;
                }
            }
        }
    }
}

// ---------------- merge 24 partial top-3 entries -----------------------------
__device__ __forceinline__ float merge_one(const float2* __restrict__ ent) {
    float t[3] = {BIG, BIG, BIG}, f[3] = {0.f, 0.f, 0.f};
#pragma unroll
    for (int k = 0; k < PARTS * 3; k++) {
        float2 c = ent[k];
        try_ins(c.x, c.y, t, f);
    }
    float d0 = fmaxf(t[0], 0.f);
    float d1 = fmaxf(t[1], 0.f);
    float d2 = fmaxf(t[2], 0.f);
    float r0 = 1.f / (d0 + 1e-8f);
    float r1 = 1.f / (d1 + 1e-8f);
    float r2 = 1.f / (d2 + 1e-8f);
    return fmaf(r0, f[0], fmaf(r1, f[1], r2 * f[2])) / (r0 + r1 + r2);
}

// ---------------- fused main kernel -----------------------------------------
__global__ void __launch_bounds__(NT, 2)
fused_kernel(const float* __restrict__ pts, float* __restrict__ out) {
    __shared__ float2 s_m[QPB * PARTS * 3];      // 24 KB merge scratch

    const int tid  = threadIdx.x;
    const int lane = tid & 31;
    const int part = tid >> 5;                   // warp id == candidate part
    const int b    = (blockIdx.x * QPB) >> 13;   // batch

    u64 c2x[Q], c2y[Q], c2z[Q], qq2[Q];
#pragma unroll
    for (int j = 0; j < Q; j++) {
        int gq = blockIdx.x * QPB + j * 32 + lane;
        float x = pts[3 * gq + 0];
        float y = pts[3 * gq + 1];
        float z = pts[3 * gq + 2];
        float qq = __fadd_rn(__fadd_rn(__fmul_rn(x, x), __fmul_rn(y, y)),
                             __fmul_rn(z, z));
        c2x[j] = dup2(-2.f * x);
        c2y[j] = dup2(-2.f * y);
        c2z[j] = dup2(-2.f * z);
        qq2[j] = dup2(qq);
    }

    float pred = 0.f;                            // meaningful for tid < QPB
    float t[Q][3], f[Q][3];

    const float* sx[3] = { g2x + b * M2, g3x + b * M3, g4x + b * M4 };
    const float* sy[3] = { g2y + b * M2, g3y + b * M3, g4y + b * M4 };
    const float* sz[3] = { g2z + b * M2, g3z + b * M3, g4z + b * M4 };
    const float* sw[3] = { g2w + b * M2, g3w + b * M3, g4w + b * M4 };
    const float* sf[3] = { g2f + b * M2, g3f + b * M3, g4f + b * M4 };
    const int    sG[3] = { M2 / (4 * PARTS), M3 / (4 * PARTS), M4 / (4 * PARTS) };

#pragma unroll 1
    for (int s = 0; s < 3; s++) {
        scan_set(sx[s], sy[s], sz[s], sw[s], sf[s], sG[s], part,
                 c2x, c2y, c2z, qq2, t, f);
#pragma unroll
        for (int j = 0; j < Q; j++) {
            int q = j * 32 + lane;
            int bse = (q * PARTS + part) * 3;
            s_m[bse + 0] = make_float2(t[j][0], f[j][0]);
            s_m[bse + 1] = make_float2(t[j][1], f[j][1]);
            s_m[bse + 2] = make_float2(t[j][2], f[j][2]);
        }
        __syncthreads();
        if (tid < QPB) pred += merge_one(s_m + tid * PARTS * 3);
        __syncthreads();
    }

    bool found[Q];
    scan_mask(gmx + b * MM, gmy + b * MM, gmz + b * MM, gmw + b * MM,
              MM / (4 * PARTS), part, c2x, c2y, c2z, qq2, found);

    float* s_fl = reinterpret_cast<float*>(s_m);
#pragma unroll
    for (int j = 0; j < Q; j++)
        s_fl[(j * 32 + lane) * PARTS + part] = found[j] ? 1.f : 0.f;
    __syncthreads();
    if (tid < QPB) {
        float fl = 0.f;
#pragma unroll
        for (int k = 0; k < PARTS; k++) fl = fmaxf(fl, s_fl[tid * PARTS + k]);
        int gq = blockIdx.x * QPB + tid;
        out[gq] = pred;                          // pred_hm (B,N,1)
        out[Bn * Nn + gq] = fl;                  // gt_hm   (B,N)
    }
}

// ---------------- launch ----------------------------------------------------
extern "C" void kernel_launch(void* const* d_in, const int* in_sizes, int n_in,
                              void* d_out, int out_size) {
    (void)in_sizes; (void)n_in; (void)out_size;
    const float* pts    = (const float*)d_in[0];
    const float* known2 = (const float*)d_in[1];
    const float* feats2 = (const float*)d_in[2];
    const float* known3 = (const float*)d_in[3];
    const float* feats3 = (const float*)d_in[4];
    const float* known4 = (const float*)d_in[5];
    const float* feats4 = (const float*)d_in[6];
    const float* matchp = (const float*)d_in[7];
    const float* w_fc   = (const float*)d_in[8];
    const float* w_cls  = (const float*)d_in[9];
    float* out = (float*)d_out;

    constexpr int total = Bn * (M2 + M3 + M4 + MM);
    precompute_kernel<<<(total + NT - 1) / NT, NT>>>(
        known2, feats2, known3, feats3, known4, feats4, matchp, w_fc, w_cls);
    fused_kernel<<<(Bn * Nn) / QPB, NT>>>(pts, out);
}